// round 4
// baseline (speedup 1.0000x reference)
#include <cuda_runtime.h>

// ---------------------------------------------------------------------------
// RticCompositionModule — collapsed computation.
// BN over the batch axis of a broadcast row == BN bias exactly, so all 32
// vmap slices are identical: compute ONE [32,4096] compose, broadcast x32.
//
// Round-3 GEMM: thread = 8 rows x 8 cols (LDS:FFMA2 = 1:8), 256-thread block
// covering 32 x 512, W direct LDG.128 (L1-served x4 reuse) with depth-2
// register prefetch, text GEMV folded into fusion GEMM (logical K=8192).
// ---------------------------------------------------------------------------

#define E_DIM 4096
#define H_DIM 2048
#define MROWS 32
#define BK 32

typedef unsigned long long ull;

// ---- scratch (device globals; no allocation allowed) ----
__device__ float g_xi[MROWS * E_DIM];     // relu(BN(image))
__device__ float g_xt[E_DIM];             // relu(fs_bn_b[E:2E]) (text-half BN out)
__device__ float g_part[4194304];         // split-K partials (16 MB max layout)
__device__ float g_f[MROWS * E_DIM];      // fusion output f
__device__ float g_r1[MROWS * E_DIM];     // relu(BN(gating hidden))
__device__ float g_gate[MROWS * E_DIM];   // sigmoid gate
__device__ float g_h[MROWS * H_DIM];      // ee hidden
__device__ float g_ff[MROWS * E_DIM];     // ee running residual

// ---- packed fp32x2 helpers ----
__device__ __forceinline__ ull dup2(float v) {
    ull r; asm("mov.b64 %0, {%1, %1};" : "=l"(r) : "f"(v)); return r;
}
__device__ __forceinline__ void fma2(ull& d, ull a, ull b) {
    asm("fma.rn.f32x2 %0, %1, %2, %0;" : "+l"(d) : "l"(a), "l"(b));
}

#define SEL_XI 0
#define SEL_F  1
#define SEL_R1 2
#define SEL_H  3
#define SEL_FF 4

// ---------------------------------------------------------------------------
// pre: xi = relu(BN(image)) ; xt = relu(fs_bn_b[E:2E])
// ---------------------------------------------------------------------------
__global__ void pre_kernel(const float* __restrict__ img,
                           const float* __restrict__ bng,
                           const float* __restrict__ bnb) {
    int c = blockIdx.x * blockDim.x + threadIdx.x;
    float v[MROWS];
    float s = 0.f;
#pragma unroll
    for (int m = 0; m < MROWS; ++m) { v[m] = img[m * E_DIM + c]; s += v[m]; }
    float mu = s * (1.f / 32.f);
    float s2 = 0.f;
#pragma unroll
    for (int m = 0; m < MROWS; ++m) { float d = v[m] - mu; s2 += d * d; }
    float rs = rsqrtf(s2 * (1.f / 32.f) + 1e-5f);
    float gg = bng[c], bb = bnb[c];
#pragma unroll
    for (int m = 0; m < MROWS; ++m)
        g_xi[m * E_DIM + c] = fmaxf((v[m] - mu) * rs * gg + bb, 0.f);
    g_xt[c] = fmaxf(bnb[E_DIM + c], 0.f);
}

// ---------------------------------------------------------------------------
// GEMM: part[ks][32][N] = A[32][k0:k0+kslice] @ W[k0:k0+kslice][N]
// 256 threads; rg = tid>>6 (4 row groups of 8), cg = tid&63 (8 cols each).
// Block tile 32 x 512. Per k per thread: 4 LDS.128 (A dup-pairs, broadcast),
// 2 LDG.128 (W, L1-cached across the 4 row groups), 32 FFMA2.
// fused=1: logical K = Ka + 4096, rows beyond Ka read the constant g_xt.
// ---------------------------------------------------------------------------
__global__ void __launch_bounds__(256, 2)
gemm_kernel(int aSel, const float* __restrict__ W, int Ka, int N, int kslice,
            int fused) {
    const float* A = (aSel == SEL_XI) ? g_xi
                   : (aSel == SEL_F)  ? g_f
                   : (aSel == SEL_R1) ? g_r1
                   : (aSel == SEL_H)  ? g_h
                                      : g_ff;
    __shared__ __align__(16) ull sA[BK][MROWS];   // 8 KB dup-pairs
    const int tid = threadIdx.x;
    const int rg  = tid >> 6;          // 0..3
    const int cg  = tid & 63;          // 0..63
    const int col = blockIdx.x * 512 + cg * 8;
    const int k0  = blockIdx.y * kslice;

    ull acc[8][4];
#pragma unroll
    for (int r = 0; r < 8; ++r)
#pragma unroll
        for (int p = 0; p < 4; ++p) acc[r][p] = 0ull;

    const float* wp = W + (size_t)k0 * N + col;

    // depth-2 prefetch ring for W (2x ulonglong2 per k)
    ulonglong2 wbuf[2][2];
    wbuf[0][0] = *reinterpret_cast<const ulonglong2*>(wp);
    wbuf[0][1] = *reinterpret_cast<const ulonglong2*>(wp + 4);
    wbuf[1][0] = *reinterpret_cast<const ulonglong2*>(wp + N);
    wbuf[1][1] = *reinterpret_cast<const ulonglong2*>(wp + N + 4);
    const float* wnext = wp + (size_t)2 * N;

    for (int kb = 0; kb < kslice; kb += BK) {
        __syncthreads();
        // stage A tile (dup-pairs). consecutive tid -> consecutive kk: coalesced.
#pragma unroll
        for (int i = 0; i < 4; ++i) {
            int idx = tid + i * 256;
            int kk  = idx & 31;
            int m   = idx >> 5;
            int kg  = k0 + kb + kk;
            float av = (fused && kg >= Ka) ? g_xt[kg - Ka]
                                           : A[(size_t)m * Ka + kg];
            sA[kk][m] = dup2(av);
        }
        __syncthreads();
#pragma unroll 8
        for (int kk = 0; kk < BK; ++kk) {
            int k = kb + kk;
            ulonglong2 w0 = wbuf[k & 1][0];
            ulonglong2 w1 = wbuf[k & 1][1];
            if (k + 2 < kslice) {
                wbuf[k & 1][0] = *reinterpret_cast<const ulonglong2*>(wnext);
                wbuf[k & 1][1] = *reinterpret_cast<const ulonglong2*>(wnext + 4);
            }
            wnext += N;
#pragma unroll
            for (int j = 0; j < 4; ++j) {
                ulonglong2 a2 = *reinterpret_cast<const ulonglong2*>(&sA[kk][rg * 8 + 2 * j]);
                fma2(acc[2 * j][0],     a2.x, w0.x);
                fma2(acc[2 * j][1],     a2.x, w0.y);
                fma2(acc[2 * j][2],     a2.x, w1.x);
                fma2(acc[2 * j][3],     a2.x, w1.y);
                fma2(acc[2 * j + 1][0], a2.y, w0.x);
                fma2(acc[2 * j + 1][1], a2.y, w0.y);
                fma2(acc[2 * j + 1][2], a2.y, w1.x);
                fma2(acc[2 * j + 1][3], a2.y, w1.y);
            }
        }
    }
    float* base = g_part + (size_t)blockIdx.y * MROWS * N + col;
#pragma unroll
    for (int r = 0; r < 8; ++r) {
        ulonglong2* o = reinterpret_cast<ulonglong2*>(base + (size_t)(rg * 8 + r) * N);
        o[0] = make_ulonglong2(acc[r][0], acc[r][1]);
        o[1] = make_ulonglong2(acc[r][2], acc[r][3]);
    }
}

// ---------------------------------------------------------------------------
// Elementwise reducers (scalar; one thread per output element; 512x256).
// mode 0: bias            -> g_f
// mode 1: bias, sigmoid   -> g_gate
// mode 2: bias + g_f      -> g_ff
// mode 3: bias + g_ff     -> g_ff
// ---------------------------------------------------------------------------
__global__ void reduce_elem(const float* __restrict__ bias, int ksp, int mode) {
    int idx = blockIdx.x * 256 + threadIdx.x;     // 32*4096 elements
    int c = idx & (E_DIM - 1);
    float v = bias[c];
#pragma unroll 8
    for (int sl = 0; sl < ksp; ++sl)
        v += g_part[(size_t)sl * (MROWS * E_DIM) + idx];
    if (mode == 0) {
        g_f[idx] = v;
    } else if (mode == 1) {
        g_gate[idx] = 1.f / (1.f + expf(-v));
    } else {
        v += (mode == 2) ? g_f[idx] : g_ff[idx];
        g_ff[idx] = v;
    }
}

// ---------------------------------------------------------------------------
// Fused split-K reduce + BN + ReLU. Block = 256 threads, 32 columns.
// outSel: 0 -> g_r1 (N=E), 1 -> g_h (N=H)
// ---------------------------------------------------------------------------
__global__ void reduce_bn_relu(const float* __restrict__ bias,
                               const float* __restrict__ gam,
                               const float* __restrict__ bet,
                               int N, int ksp, int outSel) {
    __shared__ float ssum[MROWS][33];
    __shared__ float smu[MROWS], srs[MROWS];
    int c  = threadIdx.x & 31;
    int mg = threadIdx.x >> 5;
    int gc = blockIdx.x * 32 + c;
    float b = bias[gc];
#pragma unroll
    for (int r = 0; r < 4; ++r) {
        int m = mg * 4 + r;
        float s = b;
        const float* p = g_part + (size_t)m * N + gc;
#pragma unroll 8
        for (int sl = 0; sl < ksp; ++sl)
            s += p[(size_t)sl * MROWS * N];
        ssum[m][c] = s;
    }
    __syncthreads();
    if (threadIdx.x < 32) {
        int cc = threadIdx.x;
        float su = 0.f;
#pragma unroll
        for (int m = 0; m < MROWS; ++m) su += ssum[m][cc];
        float mu = su * (1.f / 32.f);
        float s2 = 0.f;
#pragma unroll
        for (int m = 0; m < MROWS; ++m) { float d = ssum[m][cc] - mu; s2 += d * d; }
        smu[cc] = mu;
        srs[cc] = rsqrtf(s2 * (1.f / 32.f) + 1e-5f);
    }
    __syncthreads();
    float gg = gam[gc], bb = bet[gc];
    float* out = outSel ? g_h : g_r1;
#pragma unroll
    for (int r = 0; r < 4; ++r) {
        int m = mg * 4 + r;
        float o = (ssum[m][c] - smu[c]) * srs[c] * gg + bb;
        out[(size_t)m * N + gc] = fmaxf(o, 0.f);
    }
}

// ---------------------------------------------------------------------------
// final: R = img*g + ff*(1-g); broadcast 32x along the text axis (float4)
// ---------------------------------------------------------------------------
__global__ void final_kernel(const float* __restrict__ img, float* __restrict__ out) {
    int q = blockIdx.x * 256 + threadIdx.x;   // 32768 float4 groups
    float4 gv = *reinterpret_cast<const float4*>(&g_gate[q * 4]);
    float4 fv = *reinterpret_cast<const float4*>(&g_ff[q * 4]);
    float4 iv = *reinterpret_cast<const float4*>(&img[q * 4]);
    float4 r;
    r.x = iv.x * gv.x + fv.x * (1.f - gv.x);
    r.y = iv.y * gv.y + fv.y * (1.f - gv.y);
    r.z = iv.z * gv.z + fv.z * (1.f - gv.z);
    r.w = iv.w * gv.w + fv.w * (1.f - gv.w);
    float4* o4 = reinterpret_cast<float4*>(out);
#pragma unroll
    for (int j = 0; j < 32; ++j)
        o4[(size_t)j * 32768 + q] = r;
}

// ---------------------------------------------------------------------------
extern "C" void kernel_launch(void* const* d_in, const int* in_sizes, int n_in,
                              void* d_out, int out_size) {
    const float* img     = (const float*)d_in[0];
    // d_in[1] = text_features: provably unused (BN of broadcast row == bias)
    const float* fs_bn_g = (const float*)d_in[2];
    const float* fs_bn_b = (const float*)d_in[3];
    const float* fs_w    = (const float*)d_in[4];
    const float* fs_b    = (const float*)d_in[5];
    const float* gt_w1   = (const float*)d_in[6];
    const float* gt_b1   = (const float*)d_in[7];
    const float* gt_bn_g = (const float*)d_in[8];
    const float* gt_bn_b = (const float*)d_in[9];
    const float* gt_w2   = (const float*)d_in[10];
    const float* gt_b2   = (const float*)d_in[11];
    const float* ee_w1   = (const float*)d_in[12];
    const float* ee_b1   = (const float*)d_in[13];
    const float* ee_bn_g = (const float*)d_in[14];
    const float* ee_bn_b = (const float*)d_in[15];
    const float* ee_w2   = (const float*)d_in[16];
    const float* ee_b2   = (const float*)d_in[17];
    float* out = (float*)d_out;

    // 0) image BN + relu, constant text vector
    pre_kernel<<<16, 256>>>(img, fs_bn_g, fs_bn_b);

    // 1) fusion: f = [xi ; xt-broadcast] @ fs_w + fs_b   (logical K = 8192)
    gemm_kernel<<<dim3(8, 32), 256>>>(SEL_XI, fs_w, E_DIM, E_DIM, 256, 1);
    reduce_elem<<<512, 256>>>(fs_b, 32, 0);

    // 2) gating
    gemm_kernel<<<dim3(8, 32), 256>>>(SEL_F, gt_w1, E_DIM, E_DIM, 128, 0);
    reduce_bn_relu<<<128, 256>>>(gt_b1, gt_bn_g, gt_bn_b, E_DIM, 32, 0);
    gemm_kernel<<<dim3(8, 32), 256>>>(SEL_R1, gt_w2, E_DIM, E_DIM, 128, 0);
    reduce_elem<<<512, 256>>>(gt_b2, 32, 1);

    // 3) three error-encoding residual blocks
    for (int i = 0; i < 3; ++i) {
        gemm_kernel<<<dim3(4, 64), 256>>>((i == 0) ? SEL_F : SEL_FF,
                                          ee_w1 + (size_t)i * E_DIM * H_DIM,
                                          E_DIM, H_DIM, 64, 0);
        reduce_bn_relu<<<64, 256>>>(ee_b1 + i * H_DIM, ee_bn_g + i * H_DIM,
                                    ee_bn_b + i * H_DIM, H_DIM, 64, 1);
        gemm_kernel<<<dim3(8, 32), 256>>>(SEL_H, ee_w2 + (size_t)i * H_DIM * E_DIM,
                                          H_DIM, E_DIM, 64, 0);
        reduce_elem<<<512, 256>>>(ee_b2 + i * E_DIM, 32, (i == 0) ? 2 : 3);
    }

    // 4) gate-combine and broadcast to [32, 32, 4096]
    final_kernel<<<128, 256>>>(img, out);

    (void)in_sizes; (void)n_in; (void)out_size;
}